// round 9
// baseline (speedup 1.0000x reference)
#include <cuda_runtime.h>
#include <cuda_fp16.h>
#include <cstdint>

#define NN 50000
#define EE 800000
#define HF 128    // feature/hidden dim
#define CAP 64    // bucket capacity per node (Poisson(16); P(>64) ~ 1e-20)

// ---- scratch (device globals; no allocation allowed) ----
__device__ __half g_y16[NN * HF];  // messages
__device__ __half g_h16[NN * HF];  // layer-1 output (fp16)
__device__ float  g_dinv[NN];
__device__ int    g_cnt[NN];
__device__ int    g_col[NN * CAP]; // bucket storage

// ---------------- bucket build (single atomic pass) ----------------
__global__ void k_fill_bucket(const int* __restrict__ src,
                              const int* __restrict__ dst, int e) {
    int i = blockIdx.x * blockDim.x + threadIdx.x;
    if (i < e) {
        int d = dst[i];
        int p = atomicAdd(&g_cnt[d], 1);
        if (p < CAP) g_col[d * CAP + p] = src[i];
    }
}

__global__ void k_dinv(int n) {
    int i = blockIdx.x * blockDim.x + threadIdx.x;
    if (i < n) g_dinv[i] = rsqrtf((float)(g_cnt[i] + 1));  // +1 self loop
}

// ---------------- Tensor-core GEMM: Y(fp16) = X @ W [* dinv[row]] ----------------
__device__ __forceinline__ uint32_t sptr(const void* p) {
    return (uint32_t)__cvta_generic_to_shared(p);
}

template <typename T, bool SCALE>
__global__ void __launch_bounds__(256) k_gemm_tc(const T* __restrict__ X,
                                                 const float* __restrict__ W,
                                                 __half* __restrict__ Y, int n) {
    extern __shared__ __half sm[];
    __half (*As)[136] = (__half(*)[136])sm;
    __half (*Bs)[136] = (__half(*)[136])(sm + 128 * 136);
    int t = threadIdx.x;
    int block_row = blockIdx.x * 128;

    // W (fp32) -> Bs (fp16)
    {
        int r0 = t >> 5, c = (t & 31) * 4;
#pragma unroll
        for (int p = 0; p < 16; p++) {
            int r = r0 + p * 8;
            float4 wv = *(const float4*)(W + r * HF + c);
            *(__half2*)&Bs[r][c]     = __floats2half2_rn(wv.x, wv.y);
            *(__half2*)&Bs[r][c + 2] = __floats2half2_rn(wv.z, wv.w);
        }
    }
    // X -> As
    if (sizeof(T) == 4) {
        const float* Xf = (const float*)X;
        int r0 = t >> 5, c = (t & 31) * 4;
#pragma unroll
        for (int p = 0; p < 16; p++) {
            int r = r0 + p * 8;
            int gr = block_row + r;
            float4 xv = make_float4(0.f, 0.f, 0.f, 0.f);
            if (gr < n) xv = *(const float4*)(Xf + (size_t)gr * HF + c);
            *(__half2*)&As[r][c]     = __floats2half2_rn(xv.x, xv.y);
            *(__half2*)&As[r][c + 2] = __floats2half2_rn(xv.z, xv.w);
        }
    } else {
        const __half* Xh = (const __half*)X;
        int r0 = t >> 4, c = (t & 15) * 8;
#pragma unroll
        for (int p = 0; p < 8; p++) {
            int r = r0 + p * 16;
            int gr = block_row + r;
            uint4 xv = make_uint4(0, 0, 0, 0);
            if (gr < n) xv = *(const uint4*)(Xh + (size_t)gr * HF + c);
            *(uint4*)&As[r][c] = xv;
        }
    }
    __syncthreads();

    int lane = t & 31;
    int w = t >> 5;
    int mbase = (w >> 2) * 64;
    int nbase = (w & 3) * 32;

    float acc[4][4][4];
#pragma unroll
    for (int i = 0; i < 4; i++)
#pragma unroll
        for (int j = 0; j < 4; j++)
#pragma unroll
            for (int r = 0; r < 4; r++) acc[i][j][r] = 0.f;

#pragma unroll
    for (int kk = 0; kk < 8; kk++) {
        uint32_t a[4][4];
#pragma unroll
        for (int i = 0; i < 4; i++) {
            int row = mbase + i * 16 + (lane & 7) + ((lane >> 3) & 1) * 8;
            int col = kk * 16 + (lane >> 4) * 8;
            uint32_t ad = sptr(&As[row][col]);
            asm volatile("ldmatrix.sync.aligned.m8n8.x4.shared.b16 {%0,%1,%2,%3}, [%4];"
                         : "=r"(a[i][0]), "=r"(a[i][1]), "=r"(a[i][2]), "=r"(a[i][3])
                         : "r"(ad));
        }
        uint32_t b[4][2];
#pragma unroll
        for (int j = 0; j < 4; j++) {
            int row = kk * 16 + (lane & 15);
            int col = nbase + j * 8;
            uint32_t ad = sptr(&Bs[row][col]);
            asm volatile("ldmatrix.sync.aligned.m8n8.x2.trans.shared.b16 {%0,%1}, [%2];"
                         : "=r"(b[j][0]), "=r"(b[j][1])
                         : "r"(ad));
        }
#pragma unroll
        for (int i = 0; i < 4; i++)
#pragma unroll
            for (int j = 0; j < 4; j++) {
                asm volatile(
                    "mma.sync.aligned.m16n8k16.row.col.f32.f16.f16.f32 "
                    "{%0,%1,%2,%3}, {%4,%5,%6,%7}, {%8,%9}, {%0,%1,%2,%3};"
                    : "+f"(acc[i][j][0]), "+f"(acc[i][j][1]),
                      "+f"(acc[i][j][2]), "+f"(acc[i][j][3])
                    : "r"(a[i][0]), "r"(a[i][1]), "r"(a[i][2]), "r"(a[i][3]),
                      "r"(b[j][0]), "r"(b[j][1]));
            }
    }

    int g = lane >> 2, tg = lane & 3;
#pragma unroll
    for (int i = 0; i < 4; i++) {
        int r0 = block_row + mbase + i * 16 + g;
        float dv0 = 1.f, dv8 = 1.f;
        if (SCALE) {
            if (r0 < n) dv0 = g_dinv[r0];
            if (r0 + 8 < n) dv8 = g_dinv[r0 + 8];
        }
#pragma unroll
        for (int j = 0; j < 4; j++) {
            int c = nbase + j * 8 + tg * 2;
            if (r0 < n)
                *(__half2*)(Y + (size_t)r0 * HF + c) =
                    __floats2half2_rn(acc[i][j][0] * dv0, acc[i][j][1] * dv0);
            if (r0 + 8 < n)
                *(__half2*)(Y + (size_t)(r0 + 8) * HF + c) =
                    __floats2half2_rn(acc[i][j][2] * dv8, acc[i][j][3] * dv8);
        }
    }
}

// ---------------- Half-row aggregation ----------------
// Warp handles 64 features of one node: lane owns 2 feats (one uint32 of y16).
// PRESCALED: y rows already carry dinv[src] (layer 2).
template <bool PRESCALED>
__device__ __forceinline__ float2 agg_half(int node, int half, int lane, float dv) {
    const uint32_t* y1 = (const uint32_t*)g_y16;
    const size_t strider = 64;          // uint32 per row
    size_t loff = (size_t)half * 32 + lane;

    uint32_t sraw = __ldg(&y1[(size_t)node * strider + loff]);
    float2 self = __half22float2(*reinterpret_cast<__half2*>(&sraw));
    float2 acc;
    if (PRESCALED) acc = self;
    else acc = make_float2(self.x * dv, self.y * dv);

    const int* bucket = &g_col[node * CAP];
    int len = g_cnt[node];
    if (len > CAP) len = CAP;

    for (int b = 0; b < len; b += 32) {
        int m = len - b; if (m > 32) m = 32;   // warp-uniform
        int   sc = 0;
        float dc = 0.f;
        if (lane < m) {
            sc = __ldg(&bucket[b + lane]);
            if (!PRESCALED) dc = __ldg(&g_dinv[sc]);
        }
        int kk = 0;
        for (; kk + 7 < m; kk += 8) {
            uint32_t r[8];
            int s[8];
#pragma unroll
            for (int u = 0; u < 8; u++) {
                s[u] = __shfl_sync(0xFFFFFFFF, sc, kk + u);
                r[u] = __ldg(&y1[(size_t)s[u] * strider + loff]);
            }
#pragma unroll
            for (int u = 0; u < 8; u++) {
                float2 v = __half22float2(*reinterpret_cast<__half2*>(&r[u]));
                if (PRESCALED) { acc.x += v.x; acc.y += v.y; }
                else {
                    float d = __shfl_sync(0xFFFFFFFF, dc, kk + u);
                    acc.x = fmaf(v.x, d, acc.x);
                    acc.y = fmaf(v.y, d, acc.y);
                }
            }
        }
        for (; kk < m; kk++) {
            int sidx = __shfl_sync(0xFFFFFFFF, sc, kk);
            uint32_t raw = __ldg(&y1[(size_t)sidx * strider + loff]);
            float2 v = __half22float2(*reinterpret_cast<__half2*>(&raw));
            if (PRESCALED) { acc.x += v.x; acc.y += v.y; }
            else {
                float d = __shfl_sync(0xFFFFFFFF, dc, kk);
                acc.x = fmaf(v.x, d, acc.x);
                acc.y = fmaf(v.y, d, acc.y);
            }
        }
    }
    return acc;
}

// ---------------- Aggregate (layer 1) -> h (fp16) ----------------
__global__ void __launch_bounds__(256) k_agg(const float* __restrict__ bias, int n) {
    int gw = (blockIdx.x * blockDim.x + threadIdx.x) >> 5;
    int lane = threadIdx.x & 31;
    int node = gw >> 1, half = gw & 1;
    if (node >= n) return;
    float dv = g_dinv[node];
    float2 acc = agg_half<false>(node, half, lane, dv);
    int f = half * 64 + lane * 2;
    float2 b = *(const float2*)(bias + f);
    __half2 p = __floats2half2_rn(fmaxf(fmaf(acc.x, dv, b.x), 0.f),
                                  fmaxf(fmaf(acc.y, dv, b.y), 0.f));
    ((uint32_t*)g_h16)[(size_t)node * 64 + half * 32 + lane] =
        *reinterpret_cast<uint32_t*>(&p);
}

// ---------------- Aggregate (layer 2, prescaled) + final projection ----------------
// Each half-warp atomically adds its 64-feat partial dot into out[node].
__global__ void __launch_bounds__(256) k_agg_final(const float* __restrict__ bias,
                                                   const float* __restrict__ Wf,
                                                   const float* __restrict__ bf,
                                                   float* __restrict__ out, int n) {
    int gw = (blockIdx.x * blockDim.x + threadIdx.x) >> 5;
    int lane = threadIdx.x & 31;
    int node = gw >> 1, half = gw & 1;
    if (node >= n) return;
    float dv = g_dinv[node];
    float2 acc = agg_half<true>(node, half, lane, dv);
    int f = half * 64 + lane * 2;
    float2 b = *(const float2*)(bias + f);
    float2 w = *(const float2*)(Wf + f);
    float p = fmaxf(fmaf(acc.x, dv, b.x), 0.f) * w.x
            + fmaxf(fmaf(acc.y, dv, b.y), 0.f) * w.y;
#pragma unroll
    for (int off = 16; off > 0; off >>= 1)
        p += __shfl_xor_sync(0xFFFFFFFF, p, off);
    if (lane == 0) {
        if (half == 0) p += bf[0];
        atomicAdd(&out[node], p);
    }
}

// ---------------- launch ----------------
extern "C" void kernel_launch(void* const* d_in, const int* in_sizes, int n_in,
                              void* d_out, int out_size) {
    const float* x  = (const float*)d_in[0];
    const int*   ei = (const int*)d_in[1];
    const float* W1 = (const float*)d_in[2];
    const float* b1 = (const float*)d_in[3];
    const float* W2 = (const float*)d_in[4];
    const float* b2 = (const float*)d_in[5];
    const float* Wf = (const float*)d_in[6];
    const float* bf = (const float*)d_in[7];

    int n = in_sizes[0] / HF;     // 50000
    int e = in_sizes[1] / 2;      // 800000
    const int* src = ei;
    const int* dst = ei + e;

    void* yp; cudaGetSymbolAddress(&yp, g_y16);
    void* hp; cudaGetSymbolAddress(&hp, g_h16);
    void* cp; cudaGetSymbolAddress(&cp, g_cnt);
    __half* Y = (__half*)yp;
    __half* H = (__half*)hp;

    const int SMEM = 2 * 128 * 136 * (int)sizeof(__half);  // 69632

    static cudaStream_t s_csr = nullptr;
    static cudaEvent_t ev_fork = nullptr, ev_join = nullptr;
    if (s_csr == nullptr) {
        cudaStreamCreateWithFlags(&s_csr, cudaStreamNonBlocking);
        cudaEventCreateWithFlags(&ev_fork, cudaEventDisableTiming);
        cudaEventCreateWithFlags(&ev_join, cudaEventDisableTiming);
        cudaFuncSetAttribute((const void*)k_gemm_tc<float, false>,
                             cudaFuncAttributeMaxDynamicSharedMemorySize, SMEM);
        cudaFuncSetAttribute((const void*)k_gemm_tc<__half, true>,
                             cudaFuncAttributeMaxDynamicSharedMemorySize, SMEM);
    }

    int tb = 256;
    int gemm_blocks = (n + 127) / 128;
    int halfwarp_blocks = (n * 2 * 32 + tb - 1) / tb;

    // ---- fork: bucket build on side stream, GEMM1 on main stream ----
    cudaEventRecord(ev_fork, 0);
    cudaStreamWaitEvent(s_csr, ev_fork, 0);

    cudaMemsetAsync(cp, 0, n * sizeof(int), s_csr);
    k_fill_bucket<<<(e + tb - 1) / tb, tb, 0, s_csr>>>(src, dst, e);
    k_dinv<<<(n + tb - 1) / tb, tb, 0, s_csr>>>(n);
    cudaEventRecord(ev_join, s_csr);

    // main stream: zero the output (accumulated atomically) + layer-1 GEMM
    cudaMemsetAsync(d_out, 0, n * sizeof(float));
    k_gemm_tc<float, false><<<gemm_blocks, 256, SMEM>>>(x, W1, Y, n);

    // ---- join ----
    cudaStreamWaitEvent(0, ev_join, 0);

    // Layer 1 aggregation (writes fp16 h)
    k_agg<<<halfwarp_blocks, tb>>>(b1, n);
    // Layer 2 (epilogue prescales by dinv[row])
    k_gemm_tc<__half, true><<<gemm_blocks, 256, SMEM>>>(H, W2, Y, n);
    k_agg_final<<<halfwarp_blocks, tb>>>(b2, Wf, bf, (float*)d_out, n);
}

// round 10
// speedup vs baseline: 1.2392x; 1.2392x over previous
#include <cuda_runtime.h>
#include <cuda_fp16.h>
#include <cstdint>

#define NN 50000
#define EE 800000
#define HF 128    // feature/hidden dim
#define CAP 64    // bucket capacity per node (Poisson(16); P(>64) ~ 1e-20)

// ---- scratch (device globals; no allocation allowed) ----
__device__ __half g_y16[NN * HF];  // messages
__device__ __half g_h16[NN * HF];  // layer-1 output (fp16)
__device__ float  g_dinv[NN];
__device__ int    g_cnt[NN];
__device__ int    g_col[NN * CAP]; // bucket storage

// ---------------- bucket build (single atomic pass) ----------------
__global__ void k_fill_bucket(const int* __restrict__ src,
                              const int* __restrict__ dst, int e) {
    int i = blockIdx.x * blockDim.x + threadIdx.x;
    if (i < e) {
        int d = dst[i];
        int p = atomicAdd(&g_cnt[d], 1);
        if (p < CAP) g_col[d * CAP + p] = src[i];
    }
}

__global__ void k_dinv(int n) {
    int i = blockIdx.x * blockDim.x + threadIdx.x;
    if (i < n) g_dinv[i] = rsqrtf((float)(g_cnt[i] + 1));  // +1 self loop
}

// ---------------- Tensor-core GEMM: Y(fp16) = X @ W [* dinv[row]] ----------------
__device__ __forceinline__ uint32_t sptr(const void* p) {
    return (uint32_t)__cvta_generic_to_shared(p);
}

// rows processed: [row0, row0 + 128*gridDim.x), clipped to n
template <typename T, bool SCALE>
__global__ void __launch_bounds__(256) k_gemm_tc(const T* __restrict__ X,
                                                 const float* __restrict__ W,
                                                 __half* __restrict__ Y,
                                                 int row0, int n) {
    extern __shared__ __half sm[];
    __half (*As)[136] = (__half(*)[136])sm;
    __half (*Bs)[136] = (__half(*)[136])(sm + 128 * 136);
    int t = threadIdx.x;
    int block_row = row0 + blockIdx.x * 128;

    // W (fp32) -> Bs (fp16)
    {
        int r0 = t >> 5, c = (t & 31) * 4;
#pragma unroll
        for (int p = 0; p < 16; p++) {
            int r = r0 + p * 8;
            float4 wv = *(const float4*)(W + r * HF + c);
            *(__half2*)&Bs[r][c]     = __floats2half2_rn(wv.x, wv.y);
            *(__half2*)&Bs[r][c + 2] = __floats2half2_rn(wv.z, wv.w);
        }
    }
    // X -> As
    if (sizeof(T) == 4) {
        const float* Xf = (const float*)X;
        int r0 = t >> 5, c = (t & 31) * 4;
#pragma unroll
        for (int p = 0; p < 16; p++) {
            int r = r0 + p * 8;
            int gr = block_row + r;
            float4 xv = make_float4(0.f, 0.f, 0.f, 0.f);
            if (gr < n) xv = *(const float4*)(Xf + (size_t)gr * HF + c);
            *(__half2*)&As[r][c]     = __floats2half2_rn(xv.x, xv.y);
            *(__half2*)&As[r][c + 2] = __floats2half2_rn(xv.z, xv.w);
        }
    } else {
        const __half* Xh = (const __half*)X;
        int r0 = t >> 4, c = (t & 15) * 8;
#pragma unroll
        for (int p = 0; p < 8; p++) {
            int r = r0 + p * 16;
            int gr = block_row + r;
            uint4 xv = make_uint4(0, 0, 0, 0);
            if (gr < n) xv = *(const uint4*)(Xh + (size_t)gr * HF + c);
            *(uint4*)&As[r][c] = xv;
        }
    }
    __syncthreads();

    int lane = t & 31;
    int w = t >> 5;
    int mbase = (w >> 2) * 64;
    int nbase = (w & 3) * 32;

    float acc[4][4][4];
#pragma unroll
    for (int i = 0; i < 4; i++)
#pragma unroll
        for (int j = 0; j < 4; j++)
#pragma unroll
            for (int r = 0; r < 4; r++) acc[i][j][r] = 0.f;

#pragma unroll
    for (int kk = 0; kk < 8; kk++) {
        uint32_t a[4][4];
#pragma unroll
        for (int i = 0; i < 4; i++) {
            int row = mbase + i * 16 + (lane & 7) + ((lane >> 3) & 1) * 8;
            int col = kk * 16 + (lane >> 4) * 8;
            uint32_t ad = sptr(&As[row][col]);
            asm volatile("ldmatrix.sync.aligned.m8n8.x4.shared.b16 {%0,%1,%2,%3}, [%4];"
                         : "=r"(a[i][0]), "=r"(a[i][1]), "=r"(a[i][2]), "=r"(a[i][3])
                         : "r"(ad));
        }
        uint32_t b[4][2];
#pragma unroll
        for (int j = 0; j < 4; j++) {
            int row = kk * 16 + (lane & 15);
            int col = nbase + j * 8;
            uint32_t ad = sptr(&Bs[row][col]);
            asm volatile("ldmatrix.sync.aligned.m8n8.x2.trans.shared.b16 {%0,%1}, [%2];"
                         : "=r"(b[j][0]), "=r"(b[j][1])
                         : "r"(ad));
        }
#pragma unroll
        for (int i = 0; i < 4; i++)
#pragma unroll
            for (int j = 0; j < 4; j++) {
                asm volatile(
                    "mma.sync.aligned.m16n8k16.row.col.f32.f16.f16.f32 "
                    "{%0,%1,%2,%3}, {%4,%5,%6,%7}, {%8,%9}, {%0,%1,%2,%3};"
                    : "+f"(acc[i][j][0]), "+f"(acc[i][j][1]),
                      "+f"(acc[i][j][2]), "+f"(acc[i][j][3])
                    : "r"(a[i][0]), "r"(a[i][1]), "r"(a[i][2]), "r"(a[i][3]),
                      "r"(b[j][0]), "r"(b[j][1]));
            }
    }

    int g = lane >> 2, tg = lane & 3;
#pragma unroll
    for (int i = 0; i < 4; i++) {
        int r0 = block_row + mbase + i * 16 + g;
        float dv0 = 1.f, dv8 = 1.f;
        if (SCALE) {
            if (r0 < n) dv0 = g_dinv[r0];
            if (r0 + 8 < n) dv8 = g_dinv[r0 + 8];
        }
#pragma unroll
        for (int j = 0; j < 4; j++) {
            int c = nbase + j * 8 + tg * 2;
            if (r0 < n)
                *(__half2*)(Y + (size_t)r0 * HF + c) =
                    __floats2half2_rn(acc[i][j][0] * dv0, acc[i][j][1] * dv0);
            if (r0 + 8 < n)
                *(__half2*)(Y + (size_t)(r0 + 8) * HF + c) =
                    __floats2half2_rn(acc[i][j][2] * dv8, acc[i][j][3] * dv8);
        }
    }
}

// gather one fp16 row fragment (4 feats) as float4
__device__ __forceinline__ float4 ld_row4(const uint2* __restrict__ y2,
                                          int node, int lane) {
    uint2 raw = __ldg(&y2[(size_t)node * 32 + lane]);
    __half2 a = *reinterpret_cast<const __half2*>(&raw.x);
    __half2 b = *reinterpret_cast<const __half2*>(&raw.y);
    float2 f0 = __half22float2(a);
    float2 f1 = __half22float2(b);
    return make_float4(f0.x, f0.y, f1.x, f1.y);
}

__device__ __forceinline__ void acc_fma(float4& acc, const float4 v, float d) {
    acc.x = fmaf(v.x, d, acc.x); acc.y = fmaf(v.y, d, acc.y);
    acc.z = fmaf(v.z, d, acc.z); acc.w = fmaf(v.w, d, acc.w);
}
__device__ __forceinline__ void acc_add(float4& acc, const float4 v) {
    acc.x += v.x; acc.y += v.y; acc.z += v.z; acc.w += v.w;
}

// Batched agg body (R8 form — best known). PRESCALED: y rows carry dinv[src].
template <bool PRESCALED>
__device__ __forceinline__ float4 agg_body(int node, int lane, float dv) {
    const uint2* y2 = (const uint2*)g_y16;
    float4 self = ld_row4(y2, node, lane);
    float4 acc;
    if (PRESCALED) acc = self;
    else acc = make_float4(self.x * dv, self.y * dv, self.z * dv, self.w * dv);

    const int* bucket = &g_col[node * CAP];
    int len = g_cnt[node];
    if (len > CAP) len = CAP;

    for (int b = 0; b < len; b += 32) {
        int m = len - b; if (m > 32) m = 32;   // warp-uniform
        int   sc = 0;
        float dc = 0.f;
        if (lane < m) {
            sc = __ldg(&bucket[b + lane]);     // coalesced batch of indices
            if (!PRESCALED) dc = __ldg(&g_dinv[sc]);
        }
        int kk = 0;
        for (; kk + 3 < m; kk += 4) {
            int s0 = __shfl_sync(0xFFFFFFFF, sc, kk);
            int s1 = __shfl_sync(0xFFFFFFFF, sc, kk + 1);
            int s2 = __shfl_sync(0xFFFFFFFF, sc, kk + 2);
            int s3 = __shfl_sync(0xFFFFFFFF, sc, kk + 3);
            float4 v0 = ld_row4(y2, s0, lane);
            float4 v1 = ld_row4(y2, s1, lane);
            float4 v2 = ld_row4(y2, s2, lane);
            float4 v3 = ld_row4(y2, s3, lane);
            if (PRESCALED) {
                acc_add(acc, v0); acc_add(acc, v1);
                acc_add(acc, v2); acc_add(acc, v3);
            } else {
                float d0 = __shfl_sync(0xFFFFFFFF, dc, kk);
                float d1 = __shfl_sync(0xFFFFFFFF, dc, kk + 1);
                float d2 = __shfl_sync(0xFFFFFFFF, dc, kk + 2);
                float d3 = __shfl_sync(0xFFFFFFFF, dc, kk + 3);
                acc_fma(acc, v0, d0); acc_fma(acc, v1, d1);
                acc_fma(acc, v2, d2); acc_fma(acc, v3, d3);
            }
        }
        for (; kk < m; kk++) {
            int s0 = __shfl_sync(0xFFFFFFFF, sc, kk);
            float4 v0 = ld_row4(y2, s0, lane);
            if (PRESCALED) acc_add(acc, v0);
            else {
                float d0 = __shfl_sync(0xFFFFFFFF, dc, kk);
                acc_fma(acc, v0, d0);
            }
        }
    }
    return acc;
}

// ---------------- Aggregate (layer 1) -> h (fp16), nodes [node0, node1) ----------------
__global__ void __launch_bounds__(256) k_agg(const float* __restrict__ bias,
                                             int node0, int node1) {
    int node = node0 + ((blockIdx.x * blockDim.x + threadIdx.x) >> 5);
    int lane = threadIdx.x & 31;
    if (node >= node1) return;
    float dv = g_dinv[node];
    float4 acc = agg_body<false>(node, lane, dv);
    float4 b = *(const float4*)(bias + lane * 4);
    __half2 p0 = __floats2half2_rn(fmaxf(fmaf(acc.x, dv, b.x), 0.f),
                                   fmaxf(fmaf(acc.y, dv, b.y), 0.f));
    __half2 p1 = __floats2half2_rn(fmaxf(fmaf(acc.z, dv, b.z), 0.f),
                                   fmaxf(fmaf(acc.w, dv, b.w), 0.f));
    uint2 pk;
    pk.x = *reinterpret_cast<uint32_t*>(&p0);
    pk.y = *reinterpret_cast<uint32_t*>(&p1);
    ((uint2*)g_h16)[(size_t)node * 32 + lane] = pk;
}

// ---------------- Aggregate (layer 2, prescaled y) + final projection ----------------
__global__ void __launch_bounds__(256) k_agg_final(const float* __restrict__ bias,
                                                   const float* __restrict__ Wf,
                                                   const float* __restrict__ bf,
                                                   float* __restrict__ out, int n) {
    int node = (blockIdx.x * blockDim.x + threadIdx.x) >> 5;
    int lane = threadIdx.x & 31;
    if (node >= n) return;
    float dv = g_dinv[node];
    float4 acc = agg_body<true>(node, lane, dv);
    float4 b = *(const float4*)(bias + lane * 4);
    float4 w = ((const float4*)Wf)[lane];
    float p = fmaxf(fmaf(acc.x, dv, b.x), 0.f) * w.x
            + fmaxf(fmaf(acc.y, dv, b.y), 0.f) * w.y
            + fmaxf(fmaf(acc.z, dv, b.z), 0.f) * w.z
            + fmaxf(fmaf(acc.w, dv, b.w), 0.f) * w.w;
#pragma unroll
    for (int off = 16; off > 0; off >>= 1)
        p += __shfl_xor_sync(0xFFFFFFFF, p, off);
    if (lane == 0) out[node] = p + bf[0];
}

// ---------------- launch ----------------
extern "C" void kernel_launch(void* const* d_in, const int* in_sizes, int n_in,
                              void* d_out, int out_size) {
    const float* x  = (const float*)d_in[0];
    const int*   ei = (const int*)d_in[1];
    const float* W1 = (const float*)d_in[2];
    const float* b1 = (const float*)d_in[3];
    const float* W2 = (const float*)d_in[4];
    const float* b2 = (const float*)d_in[5];
    const float* Wf = (const float*)d_in[6];
    const float* bf = (const float*)d_in[7];

    int n = in_sizes[0] / HF;     // 50000
    int e = in_sizes[1] / 2;      // 800000
    const int* src = ei;
    const int* dst = ei + e;

    void* yp; cudaGetSymbolAddress(&yp, g_y16);
    void* hp; cudaGetSymbolAddress(&hp, g_h16);
    void* cp; cudaGetSymbolAddress(&cp, g_cnt);
    __half* Y = (__half*)yp;
    __half* H = (__half*)hp;

    const int SMEM = 2 * 128 * 136 * (int)sizeof(__half);  // 69632

    static cudaStream_t s1 = nullptr;
    static cudaEvent_t ev_fork = nullptr, ev_csr = nullptr,
                       ev_g1 = nullptr, ev_a1b = nullptr;
    if (s1 == nullptr) {
        cudaStreamCreateWithFlags(&s1, cudaStreamNonBlocking);
        cudaEventCreateWithFlags(&ev_fork, cudaEventDisableTiming);
        cudaEventCreateWithFlags(&ev_csr, cudaEventDisableTiming);
        cudaEventCreateWithFlags(&ev_g1, cudaEventDisableTiming);
        cudaEventCreateWithFlags(&ev_a1b, cudaEventDisableTiming);
        cudaFuncSetAttribute((const void*)k_gemm_tc<float, false>,
                             cudaFuncAttributeMaxDynamicSharedMemorySize, SMEM);
        cudaFuncSetAttribute((const void*)k_gemm_tc<__half, true>,
                             cudaFuncAttributeMaxDynamicSharedMemorySize, SMEM);
    }

    int tb = 256;
    // node split for pipelining (multiple of 128 for clean GEMM tiles)
    int nA = (((n / 2) + 127) / 128) * 128;
    if (nA > n) nA = n;
    int nB = n - nA;

    auto wblocks = [tb](int cnt) { return (cnt * 32 + tb - 1) / tb; };

    // ---- fork ----
    cudaEventRecord(ev_fork, 0);
    cudaStreamWaitEvent(s1, ev_fork, 0);

    // s1: bucket build
    cudaMemsetAsync(cp, 0, n * sizeof(int), s1);
    k_fill_bucket<<<(e + tb - 1) / tb, tb, 0, s1>>>(src, dst, e);
    k_dinv<<<(n + tb - 1) / tb, tb, 0, s1>>>(n);
    cudaEventRecord(ev_csr, s1);

    // s0: layer-1 GEMM (independent of graph structure)
    k_gemm_tc<float, false><<<(n + 127) / 128, 256, SMEM>>>(x, W1, Y, 0, n);
    cudaEventRecord(ev_g1, 0);

    // s0: agg1 for node range A (needs CSR + GEMM1)
    cudaStreamWaitEvent(0, ev_csr, 0);
    k_agg<<<wblocks(nA), tb>>>(b1, 0, nA);

    // s1: agg1 for node range B (needs CSR [already on s1] + GEMM1)
    cudaStreamWaitEvent(s1, ev_g1, 0);
    k_agg<<<wblocks(nB), tb, 0, s1>>>(b1, nA, n);
    cudaEventRecord(ev_a1b, s1);

    // s0: GEMM2 on rows [0, nA) — depends only on agg1_A (+dinv, done)
    k_gemm_tc<__half, true><<<nA / 128, 256, SMEM>>>(H, W2, Y, 0, n);

    // s0: GEMM2 on rows [nA, n) — needs agg1_B
    cudaStreamWaitEvent(0, ev_a1b, 0);
    k_gemm_tc<__half, true><<<(nB + 127) / 128, 256, SMEM>>>(H, W2, Y, nA, n);

    // s0: final aggregation + projection over all nodes
    k_agg_final<<<wblocks(n), tb>>>(b2, Wf, bf, (float*)d_out, n);
}